// round 4
// baseline (speedup 1.0000x reference)
#include <cuda_runtime.h>
#include <math.h>

#define Bn 256
#define Mn 512
#define Dn 512
#define Cn 8
#define U1 512
#define U2 256
#define U3 128

typedef unsigned long long u64;

// Scratch (device-code-only references)
__device__ float g_pool4[4 * Bn * Dn];       // (q, B, D) partial pools
__device__ float g_h1[Cn * Bn * U1];         // (C, B, 512)
__device__ float g_h2[Cn * Bn * U2];         // (C, B, 256)
__device__ float g_term[Cn * Bn];            // per (c,b) loss term

// packed dual-fp32 FMA (sm_103a FFMA2; PTX-only path, exact fp32 semantics)
__device__ __forceinline__ void fma2(u64& d, u64 a, u64 b, u64 c) {
    asm("fma.rn.f32x2 %0, %1, %2, %3;" : "=l"(d) : "l"(a), "l"(b), "l"(c));
}
__device__ __forceinline__ u64 pack2(float x) {
    u64 r;
    asm("mov.b64 %0, {%1, %1};" : "=l"(r) : "r"(__float_as_uint(x)));
    return r;
}
__device__ __forceinline__ float2 unpack2(u64 v) {
    float2 r;
    asm("mov.b64 {%0, %1}, %2;" : "=f"(r.x), "=f"(r.y) : "l"(v));
    return r;
}

// ---------------------------------------------------------------------------
// 1) Masked sum pooling, m-split x4 into partials for wave balance.
//    grid (B, 4), 128 threads; thread t owns d = 4t..4t+3 (float4).
// ---------------------------------------------------------------------------
__global__ __launch_bounds__(128) void pool_kernel(const float* __restrict__ ec,
                                                   const float* __restrict__ mask) {
    const int b = blockIdx.x;
    const int q = blockIdx.y;
    const int tid = threadIdx.x;

    __shared__ float keep[128];
    keep[tid] = (mask[b * Mn + q * 128 + tid] == 0.0f) ? 1.0f : 0.0f;
    __syncthreads();

    const float* base = ec + ((size_t)b * Mn + q * 128) * Dn;
    float4 acc = {0.f, 0.f, 0.f, 0.f};
#pragma unroll 8
    for (int m = 0; m < 128; m++) {
        float4 v = ((const float4*)(base + (size_t)m * Dn))[tid];
        const float km = keep[m];
        acc.x = fmaf(v.x, km, acc.x);
        acc.y = fmaf(v.y, km, acc.y);
        acc.z = fmaf(v.z, km, acc.z);
        acc.w = fmaf(v.w, km, acc.w);
    }
    ((float4*)(g_pool4 + ((size_t)q * Bn + b) * Dn))[tid] = acc;
}

// ---------------------------------------------------------------------------
// 2) GEMM1: out 64(b) x 128(n) tile, K=512, kstep 32, 256 thr, 4x8 microtile
//    via f32x2. A = fixed-order sum of 4 pool partials (deterministic).
// ---------------------------------------------------------------------------
__global__ __launch_bounds__(256) void gemm1_kernel(const float* __restrict__ W,
                                                    const float* __restrict__ bias) {
    constexpr int K = Dn, NF = U1;          // full N stride 512
    const int c  = blockIdx.z;
    const int b0 = blockIdx.y * 64;
    const int n0 = blockIdx.x * 128;
    const int tid = threadIdx.x;
    const int tb = tid >> 4;                // 0..15 -> rows tb*4..
    const int tn = tid & 15;                // 0..15 -> cols tn*8..

    __shared__ float As[32][68];            // [k][b]
    __shared__ float Ws[32][128];           // [k][n]

    u64 acc2[4][4] = {};                    // 4 rows x 4 col-pairs

    const int arow = tid >> 2;              // 0..63
    const int acol = (tid & 3) * 8;         // 0,8,16,24
    const float* Wg = W + (size_t)c * K * NF + n0;
    const int wrow = tid >> 5;              // for W staging via linear f

    auto loadA = [&](int k0, float4& a0, float4& a1) {
        a0 = make_float4(0.f, 0.f, 0.f, 0.f);
        a1 = a0;
#pragma unroll
        for (int q = 0; q < 4; q++) {
            const float* P = g_pool4 + ((size_t)q * Bn + b0 + arow) * Dn + k0 + acol;
            float4 p0 = *(const float4*)P;
            float4 p1 = *(const float4*)(P + 4);
            a0.x += p0.x; a0.y += p0.y; a0.z += p0.z; a0.w += p0.w;
            a1.x += p1.x; a1.y += p1.y; a1.z += p1.z; a1.w += p1.w;
        }
    };

    float4 a0, a1, wreg[4];
    loadA(0, a0, a1);
#pragma unroll
    for (int it = 0; it < 4; it++) {
        const int f = it * 256 + tid;
        wreg[it] = *(const float4*)(Wg + (size_t)(f >> 5) * NF + (f & 31) * 4);
    }

    for (int k0 = 0; k0 < K; k0 += 32) {
        __syncthreads();
        As[acol + 0][arow] = a0.x; As[acol + 1][arow] = a0.y;
        As[acol + 2][arow] = a0.z; As[acol + 3][arow] = a0.w;
        As[acol + 4][arow] = a1.x; As[acol + 5][arow] = a1.y;
        As[acol + 6][arow] = a1.z; As[acol + 7][arow] = a1.w;
#pragma unroll
        for (int it = 0; it < 4; it++) {
            const int f = it * 256 + tid;
            *(float4*)&Ws[f >> 5][(f & 31) * 4] = wreg[it];
        }
        __syncthreads();

        if (k0 + 32 < K) {
            loadA(k0 + 32, a0, a1);
#pragma unroll
            for (int it = 0; it < 4; it++) {
                const int f = it * 256 + tid;
                wreg[it] = *(const float4*)(Wg + (size_t)(k0 + 32 + (f >> 5)) * NF + (f & 31) * 4);
            }
        }

#pragma unroll
        for (int k = 0; k < 32; k++) {
            float4 av = *(const float4*)&As[k][tb * 4];
            ulonglong2 w01 = *(const ulonglong2*)&Ws[k][tn * 8];
            ulonglong2 w23 = *(const ulonglong2*)&Ws[k][tn * 8 + 4];
            float a[4] = {av.x, av.y, av.z, av.w};
#pragma unroll
            for (int i = 0; i < 4; i++) {
                u64 ap = pack2(a[i]);
                fma2(acc2[i][0], ap, w01.x, acc2[i][0]);
                fma2(acc2[i][1], ap, w01.y, acc2[i][1]);
                fma2(acc2[i][2], ap, w23.x, acc2[i][2]);
                fma2(acc2[i][3], ap, w23.y, acc2[i][3]);
            }
        }
    }

    const float* bp = bias + c * NF + n0 + tn * 8;
    float bb[8];
#pragma unroll
    for (int j = 0; j < 8; j++) bb[j] = bp[j];
#pragma unroll
    for (int i = 0; i < 4; i++) {
        float o[8];
#pragma unroll
        for (int p = 0; p < 4; p++) {
            float2 v = unpack2(acc2[i][p]);
            o[p * 2]     = fmaxf(v.x + bb[p * 2], 0.0f);
            o[p * 2 + 1] = fmaxf(v.y + bb[p * 2 + 1], 0.0f);
        }
        float* dst = g_h1 + ((size_t)(c * Bn + b0 + tb * 4 + i)) * NF + n0 + tn * 8;
        *(float4*)dst       = make_float4(o[0], o[1], o[2], o[3]);
        *(float4*)(dst + 4) = make_float4(o[4], o[5], o[6], o[7]);
    }
}

// ---------------------------------------------------------------------------
// 3) GEMM2: 64x64 tile, K=512, 256 thr, 4x4 microtile via f32x2.
// ---------------------------------------------------------------------------
__global__ __launch_bounds__(256) void gemm2_kernel(const float* __restrict__ W,
                                                    const float* __restrict__ bias) {
    constexpr int K = U1, NF = U2;
    const int c  = blockIdx.z;
    const int b0 = blockIdx.y * 64;
    const int n0 = blockIdx.x * 64;
    const int tid = threadIdx.x;
    const int tb = tid >> 4;
    const int tn = tid & 15;

    __shared__ float As[32][68];
    __shared__ float Ws[32][68];

    u64 acc2[4][2] = {};

    const float* Ag = g_h1 + ((size_t)c * Bn + b0) * K;
    const float* Wg = W + (size_t)c * K * NF + n0;

    const int arow = tid >> 2;
    const int acol = (tid & 3) * 8;
    const int wrow = tid >> 3;              // 0..31
    const int wcol = (tid & 7) * 8;        // 0..56

    float4 a0 = *(const float4*)(Ag + (size_t)arow * K + acol);
    float4 a1 = *(const float4*)(Ag + (size_t)arow * K + acol + 4);
    float4 w0 = *(const float4*)(Wg + (size_t)wrow * NF + wcol);
    float4 w1 = *(const float4*)(Wg + (size_t)wrow * NF + wcol + 4);

    for (int k0 = 0; k0 < K; k0 += 32) {
        __syncthreads();
        As[acol + 0][arow] = a0.x; As[acol + 1][arow] = a0.y;
        As[acol + 2][arow] = a0.z; As[acol + 3][arow] = a0.w;
        As[acol + 4][arow] = a1.x; As[acol + 5][arow] = a1.y;
        As[acol + 6][arow] = a1.z; As[acol + 7][arow] = a1.w;
        *(float4*)&Ws[wrow][wcol]     = w0;
        *(float4*)&Ws[wrow][wcol + 4] = w1;
        __syncthreads();

        if (k0 + 32 < K) {
            a0 = *(const float4*)(Ag + (size_t)arow * K + k0 + 32 + acol);
            a1 = *(const float4*)(Ag + (size_t)arow * K + k0 + 32 + acol + 4);
            w0 = *(const float4*)(Wg + (size_t)(k0 + 32 + wrow) * NF + wcol);
            w1 = *(const float4*)(Wg + (size_t)(k0 + 32 + wrow) * NF + wcol + 4);
        }

#pragma unroll
        for (int k = 0; k < 32; k++) {
            float4 av = *(const float4*)&As[k][tb * 4];
            ulonglong2 wp = *(const ulonglong2*)&Ws[k][tn * 4];
            float a[4] = {av.x, av.y, av.z, av.w};
#pragma unroll
            for (int i = 0; i < 4; i++) {
                u64 ap = pack2(a[i]);
                fma2(acc2[i][0], ap, wp.x, acc2[i][0]);
                fma2(acc2[i][1], ap, wp.y, acc2[i][1]);
            }
        }
    }

    const float* bp = bias + c * NF + n0 + tn * 4;
    float bx = bp[0], by = bp[1], bz = bp[2], bw = bp[3];
#pragma unroll
    for (int i = 0; i < 4; i++) {
        float2 v0 = unpack2(acc2[i][0]);
        float2 v1 = unpack2(acc2[i][1]);
        float4 o;
        o.x = fmaxf(v0.x + bx, 0.0f);
        o.y = fmaxf(v0.y + by, 0.0f);
        o.z = fmaxf(v1.x + bz, 0.0f);
        o.w = fmaxf(v1.y + bw, 0.0f);
        *(float4*)(g_h2 + ((size_t)(c * Bn + b0 + tb * 4 + i)) * NF + n0 + tn * 4) = o;
    }
}

// ---------------------------------------------------------------------------
// 4) GEMM3 fused with L2 normalize, f32x2 inner loop.
//    Tile 16(b) x 128(n full row), K=256, 128 threads.
// ---------------------------------------------------------------------------
__global__ __launch_bounds__(128) void gemm3_norm_kernel(
        const float* __restrict__ W, const float* __restrict__ bias,
        float* __restrict__ zout) {
    constexpr int K = U2;
    constexpr int N = U3;
    const int b0 = blockIdx.x * 16;
    const int c  = blockIdx.y;
    const int tid = threadIdx.x;
    const int w = tid >> 5;
    const int lane = tid & 31;

    __shared__ float As[32][20];
    __shared__ float Ws[32][128];

    u64 acc2[4][2] = {};

    const float* Ag = g_h2 + (size_t)c * Bn * K + (size_t)b0 * K;
    const float* Wg = W + (size_t)c * K * N;

    const int arow = tid >> 3;
    const int acol = (tid & 7) * 4;

    float4 areg = *(const float4*)(Ag + (size_t)arow * K + acol);
    float4 wreg[8];
#pragma unroll
    for (int it = 0; it < 8; it++) {
        const int f = it * 128 + tid;
        wreg[it] = *(const float4*)(Wg + (size_t)(f >> 5) * N + (f & 31) * 4);
    }

    for (int k0 = 0; k0 < K; k0 += 32) {
        __syncthreads();
        As[acol + 0][arow] = areg.x; As[acol + 1][arow] = areg.y;
        As[acol + 2][arow] = areg.z; As[acol + 3][arow] = areg.w;
#pragma unroll
        for (int it = 0; it < 8; it++) {
            const int f = it * 128 + tid;
            *(float4*)&Ws[f >> 5][(f & 31) * 4] = wreg[it];
        }
        __syncthreads();

        if (k0 + 32 < K) {
            areg = *(const float4*)(Ag + (size_t)arow * K + k0 + 32 + acol);
#pragma unroll
            for (int it = 0; it < 8; it++) {
                const int f = it * 128 + tid;
                wreg[it] = *(const float4*)(Wg + (size_t)(k0 + 32 + (f >> 5)) * N + (f & 31) * 4);
            }
        }

#pragma unroll
        for (int k = 0; k < 32; k++) {
            float4 av = *(const float4*)&As[k][w * 4];
            ulonglong2 wp = *(const ulonglong2*)&Ws[k][lane * 4];
            float a[4] = {av.x, av.y, av.z, av.w};
#pragma unroll
            for (int i = 0; i < 4; i++) {
                u64 ap = pack2(a[i]);
                fma2(acc2[i][0], ap, wp.x, acc2[i][0]);
                fma2(acc2[i][1], ap, wp.y, acc2[i][1]);
            }
        }
    }

    const float* bp = bias + c * N + lane * 4;
    float bx = bp[0], by = bp[1], bz = bp[2], bw = bp[3];
#pragma unroll
    for (int i = 0; i < 4; i++) {
        float2 v0 = unpack2(acc2[i][0]);
        float2 v1 = unpack2(acc2[i][1]);
        float h0 = fmaxf(v0.x + bx, 0.0f);
        float h1 = fmaxf(v0.y + by, 0.0f);
        float h2 = fmaxf(v1.x + bz, 0.0f);
        float h3 = fmaxf(v1.y + bw, 0.0f);
        float ssq = h0 * h0 + h1 * h1 + h2 * h2 + h3 * h3;
#pragma unroll
        for (int o = 16; o; o >>= 1) ssq += __shfl_xor_sync(0xffffffffu, ssq, o);
        const float r = rsqrtf(fmaxf(ssq, 1e-12f));
        float4 o4 = {h0 * r, h1 * r, h2 * r, h3 * r};
        *(float4*)(zout + ((size_t)(c * Bn + b0 + w * 4 + i)) * N + lane * 4) = o4;
    }
}

// ---------------------------------------------------------------------------
// 5) Per-(c,b) contrastive term. grid (C, 8); 8 warps, 4 rows per warp.
// ---------------------------------------------------------------------------
#define ZPAD 132
__global__ __launch_bounds__(256) void loss_kernel(const float* __restrict__ z,
                                                   const int* __restrict__ label) {
    extern __shared__ float zs[];          // [256][ZPAD]
    __shared__ int slab[Bn];
    __shared__ int s_nump;

    const int c = blockIdx.x;
    const int tid = threadIdx.x;
    const int lane = tid & 31;
    const int warp = tid >> 5;

    const float* zc = z + (size_t)c * Bn * U3;
    for (int idx = tid; idx < Bn * U3 / 4; idx += 256) {
        const int row = idx >> 5;
        const int c4 = idx & 31;
        float4 v = *(const float4*)(zc + (size_t)row * U3 + c4 * 4);
        *(float4*)&zs[row * ZPAD + c4 * 4] = v;
    }
    slab[tid] = label[tid * Cn + c];
    __syncthreads();
    if (tid == 0) {
        int s = 0;
        for (int i = 0; i < Bn; i++) s += slab[i];
        s_nump = s;
    }
    __syncthreads();

    const int bb = blockIdx.y * 32 + warp * 4;
    const int nump = s_nump;

    int lb[4];
    const float* zb[4];
#pragma unroll
    for (int i = 0; i < 4; i++) {
        lb[i] = slab[bb + i];
        zb[i] = &zs[(bb + i) * ZPAD];
    }

    float es[4] = {0.f, 0.f, 0.f, 0.f};
    float ps[4] = {0.f, 0.f, 0.f, 0.f};

#pragma unroll
    for (int kk = 0; kk < 8; kk++) {
        const int k = kk * 32 + lane;
        const float* zk = &zs[k * ZPAD];
        float s0 = 0.f, s1 = 0.f, s2 = 0.f, s3 = 0.f;
#pragma unroll
        for (int j = 0; j < U3; j += 4) {
            float4 x = *(const float4*)(zk + j);
            float4 a0 = *(const float4*)(zb[0] + j);
            float4 a1 = *(const float4*)(zb[1] + j);
            float4 a2 = *(const float4*)(zb[2] + j);
            float4 a3 = *(const float4*)(zb[3] + j);
            s0 = fmaf(a0.x, x.x, s0); s0 = fmaf(a0.y, x.y, s0);
            s0 = fmaf(a0.z, x.z, s0); s0 = fmaf(a0.w, x.w, s0);
            s1 = fmaf(a1.x, x.x, s1); s1 = fmaf(a1.y, x.y, s1);
            s1 = fmaf(a1.z, x.z, s1); s1 = fmaf(a1.w, x.w, s1);
            s2 = fmaf(a2.x, x.x, s2); s2 = fmaf(a2.y, x.y, s2);
            s2 = fmaf(a2.z, x.z, s2); s2 = fmaf(a2.w, x.w, s2);
            s3 = fmaf(a3.x, x.x, s3); s3 = fmaf(a3.y, x.y, s3);
            s3 = fmaf(a3.z, x.z, s3); s3 = fmaf(a3.w, x.w, s3);
        }
        const int sk = slab[k];
        float sv[4] = {s0, s1, s2, s3};
#pragma unroll
        for (int i = 0; i < 4; i++) {
            const float ipv = (k == bb + i) ? 0.0f : sv[i] * 2.0f;  // /TEMP
            es[i] += __expf(ipv);
            if (sk == lb[i]) ps[i] += ipv;
        }
    }

#pragma unroll
    for (int i = 0; i < 4; i++) {
#pragma unroll
        for (int o = 16; o; o >>= 1) {
            es[i] += __shfl_xor_sync(0xffffffffu, es[i], o);
            ps[i] += __shfl_xor_sync(0xffffffffu, ps[i], o);
        }
    }
    if (lane == 0) {
#pragma unroll
        for (int i = 0; i < 4; i++) {
            const int numv = lb[i] ? nump : (Bn - nump);
            g_term[c * Bn + bb + i] = ps[i] / (float)numv - logf(es[i]);
        }
    }
}

// ---------------------------------------------------------------------------
// 6) Reduce terms -> losses[c]
// ---------------------------------------------------------------------------
__global__ void final_kernel(float* __restrict__ out) {
    __shared__ float red[Bn];
    const int c = blockIdx.x;
    const int tid = threadIdx.x;
    red[tid] = g_term[c * Bn + tid];
    __syncthreads();
    for (int s = 128; s; s >>= 1) {
        if (tid < s) red[tid] += red[tid + s];
        __syncthreads();
    }
    if (tid == 0) out[(size_t)Cn * Bn * U3 + c] = -red[0];
}

// ---------------------------------------------------------------------------
extern "C" void kernel_launch(void* const* d_in, const int* in_sizes, int n_in,
                              void* d_out, int out_size) {
    const float* ec    = (const float*)d_in[0];
    const float* mask  = (const float*)d_in[1];
    const int*   label = (const int*)d_in[2];
    const float* W1    = (const float*)d_in[3];
    const float* b1    = (const float*)d_in[4];
    const float* W2    = (const float*)d_in[5];
    const float* b2    = (const float*)d_in[6];
    const float* W3    = (const float*)d_in[7];
    const float* b3    = (const float*)d_in[8];
    float* out = (float*)d_out;

    const int loss_smem = Bn * ZPAD * (int)sizeof(float);
    cudaFuncSetAttribute(loss_kernel,
                         cudaFuncAttributeMaxDynamicSharedMemorySize, loss_smem);

    pool_kernel<<<dim3(Bn, 4), 128>>>(ec, mask);
    gemm1_kernel<<<dim3(U1 / 128, Bn / 64, Cn), 256>>>(W1, b1);
    gemm2_kernel<<<dim3(U2 / 64, Bn / 64, Cn), 256>>>(W2, b2);
    gemm3_norm_kernel<<<dim3(Bn / 16, Cn), 128>>>(W3, b3, out);
    loss_kernel<<<dim3(Cn, Bn / 32), 256, loss_smem>>>(out, label);
    final_kernel<<<Cn, Bn>>>(out);
}

// round 5
// speedup vs baseline: 1.4253x; 1.4253x over previous
#include <cuda_runtime.h>
#include <math.h>

#define Bn 256
#define Mn 512
#define Dn 512
#define Cn 8
#define U1 512
#define U2 256
#define U3 128

// Scratch (device-code-only references; never touched from host code)
__device__ float g_pooled[Bn * Dn];          // (B, D)
__device__ float g_h1[Cn * Bn * U1];         // (C, B, 512)
__device__ float g_h2[Cn * Bn * U2];         // (C, B, 256)
__device__ float g_term[Cn * Bn];            // per (c,b) loss term

// ---------------------------------------------------------------------------
// 1) Masked sum pooling: pooled[b,d] = sum_m ec[b,m,d] * (mask[b,m]==0)
//    grid (B, 2), 256 threads. 4 independent accumulators break the FMA
//    dependence chain.
// ---------------------------------------------------------------------------
__global__ __launch_bounds__(256) void pool_kernel(const float* __restrict__ ec,
                                                   const float* __restrict__ mask) {
    const int b = blockIdx.x;
    const int dbase = blockIdx.y * 256;
    const int tid = threadIdx.x;

    __shared__ float keep[Mn];
    for (int i = tid; i < Mn; i += 256)
        keep[i] = (mask[b * Mn + i] == 0.0f) ? 1.0f : 0.0f;
    __syncthreads();

    const float* p = ec + ((size_t)b * Mn) * Dn + dbase + tid;
    float a0 = 0.f, a1 = 0.f, a2 = 0.f, a3 = 0.f;
#pragma unroll 4
    for (int m = 0; m < Mn; m += 4) {
        a0 = fmaf(p[(size_t)(m + 0) * Dn], keep[m + 0], a0);
        a1 = fmaf(p[(size_t)(m + 1) * Dn], keep[m + 1], a1);
        a2 = fmaf(p[(size_t)(m + 2) * Dn], keep[m + 2], a2);
        a3 = fmaf(p[(size_t)(m + 3) * Dn], keep[m + 3], a3);
    }
    g_pooled[b * Dn + dbase + tid] = (a0 + a1) + (a2 + a3);
}

// ---------------------------------------------------------------------------
// 2) Layers 1+2: round-1 proven kernel. 64x64 tile, K-step 32, 256 threads,
//    4x4 micro-tile.
// ---------------------------------------------------------------------------
template <int LAYER>
__global__ __launch_bounds__(256) void gemm_relu_kernel(
        const float* __restrict__ W, const float* __restrict__ bias) {
    constexpr int K = (LAYER == 1) ? Dn : U1;
    constexpr int N = (LAYER == 1) ? U1 : U2;
    constexpr bool AHASC = (LAYER != 1);
    const float* Aroot = (LAYER == 1) ? g_pooled : g_h1;
    float* Oroot       = (LAYER == 1) ? g_h1     : g_h2;

    const int c  = blockIdx.z;
    const int b0 = blockIdx.y * 64;
    const int n0 = blockIdx.x * 64;
    const int tid = threadIdx.x;
    const int tb = tid >> 4;       // 0..15
    const int tn = tid & 15;       // 0..15

    __shared__ float As[32][68];   // [k][b]
    __shared__ float Ws[32][68];   // [k][n]

    float acc[4][4] = {};

    const float* Ag = Aroot + (AHASC ? (size_t)c * Bn * K : 0) + (size_t)b0 * K;
    const float* Wg = W + (size_t)c * K * N + n0;

    const int arow = tid >> 2;          // 0..63
    const int acol = (tid & 3) * 8;     // 0..24
    const int wrow = tid >> 3;          // 0..31
    const int wcol = (tid & 7) * 8;     // 0..56

    for (int k0 = 0; k0 < K; k0 += 32) {
        float4 a0 = *(const float4*)(Ag + (size_t)arow * K + k0 + acol);
        float4 a1 = *(const float4*)(Ag + (size_t)arow * K + k0 + acol + 4);
        float4 w0 = *(const float4*)(Wg + (size_t)(k0 + wrow) * N + wcol);
        float4 w1 = *(const float4*)(Wg + (size_t)(k0 + wrow) * N + wcol + 4);

        __syncthreads();
        As[acol + 0][arow] = a0.x; As[acol + 1][arow] = a0.y;
        As[acol + 2][arow] = a0.z; As[acol + 3][arow] = a0.w;
        As[acol + 4][arow] = a1.x; As[acol + 5][arow] = a1.y;
        As[acol + 6][arow] = a1.z; As[acol + 7][arow] = a1.w;
        *(float4*)&Ws[wrow][wcol]     = w0;
        *(float4*)&Ws[wrow][wcol + 4] = w1;
        __syncthreads();

#pragma unroll
        for (int k = 0; k < 32; k++) {
            float4 av = *(const float4*)&As[k][tb * 4];
            float4 wv = *(const float4*)&Ws[k][tn * 4];
            float a[4] = {av.x, av.y, av.z, av.w};
            float w[4] = {wv.x, wv.y, wv.z, wv.w};
#pragma unroll
            for (int i = 0; i < 4; i++)
#pragma unroll
                for (int j = 0; j < 4; j++)
                    acc[i][j] = fmaf(a[i], w[j], acc[i][j]);
        }
    }

    const float* bptr = bias + c * N + n0 + tn * 4;
    float bx = bptr[0], by = bptr[1], bz = bptr[2], bw = bptr[3];
#pragma unroll
    for (int i = 0; i < 4; i++) {
        const int b = b0 + tb * 4 + i;
        float4 o;
        o.x = fmaxf(acc[i][0] + bx, 0.0f);
        o.y = fmaxf(acc[i][1] + by, 0.0f);
        o.z = fmaxf(acc[i][2] + bz, 0.0f);
        o.w = fmaxf(acc[i][3] + bw, 0.0f);
        *(float4*)(Oroot + ((size_t)(c * Bn + b)) * N + n0 + tn * 4) = o;
    }
}

// ---------------------------------------------------------------------------
// 3) Layer 3 fused with L2 normalize (round-3 proven version, 11.6us).
//    Tile 16(b) x 128(n full row), K=256, 128 threads, register prefetch.
// ---------------------------------------------------------------------------
__global__ __launch_bounds__(128) void gemm3_norm_kernel(
        const float* __restrict__ W, const float* __restrict__ bias,
        float* __restrict__ zout) {
    constexpr int K = U2;   // 256
    constexpr int N = U3;   // 128
    const int b0 = blockIdx.x * 16;
    const int c  = blockIdx.y;
    const int tid = threadIdx.x;
    const int w = tid >> 5;
    const int lane = tid & 31;

    __shared__ float As[32][20];
    __shared__ float Ws[32][128];

    float acc[4][4] = {};

    const float* Ag = g_h2 + (size_t)c * Bn * K + (size_t)b0 * K;
    const float* Wg = W + (size_t)c * K * N;

    const int arow = tid >> 3;       // 0..15
    const int acol = (tid & 7) * 4;  // 0..28

    float4 areg = *(const float4*)(Ag + (size_t)arow * K + acol);
    float4 wreg[8];
#pragma unroll
    for (int it = 0; it < 8; it++) {
        const int f = it * 128 + tid;
        wreg[it] = *(const float4*)(Wg + (size_t)(f >> 5) * N + (f & 31) * 4);
    }

    for (int k0 = 0; k0 < K; k0 += 32) {
        __syncthreads();
        As[acol + 0][arow] = areg.x; As[acol + 1][arow] = areg.y;
        As[acol + 2][arow] = areg.z; As[acol + 3][arow] = areg.w;
#pragma unroll
        for (int it = 0; it < 8; it++) {
            const int f = it * 128 + tid;
            *(float4*)&Ws[f >> 5][(f & 31) * 4] = wreg[it];
        }
        __syncthreads();

        if (k0 + 32 < K) {
            areg = *(const float4*)(Ag + (size_t)arow * K + k0 + 32 + acol);
#pragma unroll
            for (int it = 0; it < 8; it++) {
                const int f = it * 128 + tid;
                wreg[it] = *(const float4*)(Wg + (size_t)(k0 + 32 + (f >> 5)) * N + (f & 31) * 4);
            }
        }

#pragma unroll
        for (int k = 0; k < 32; k++) {
            float4 av = *(const float4*)&As[k][w * 4];
            float4 wv = *(const float4*)&Ws[k][lane * 4];
            float a[4] = {av.x, av.y, av.z, av.w};
            float ww[4] = {wv.x, wv.y, wv.z, wv.w};
#pragma unroll
            for (int i = 0; i < 4; i++)
#pragma unroll
                for (int j = 0; j < 4; j++)
                    acc[i][j] = fmaf(a[i], ww[j], acc[i][j]);
        }
    }

    const float* bptr = bias + c * N + lane * 4;
    float bx = bptr[0], by = bptr[1], bz = bptr[2], bw = bptr[3];
#pragma unroll
    for (int i = 0; i < 4; i++) {
        float h0 = fmaxf(acc[i][0] + bx, 0.0f);
        float h1 = fmaxf(acc[i][1] + by, 0.0f);
        float h2 = fmaxf(acc[i][2] + bz, 0.0f);
        float h3 = fmaxf(acc[i][3] + bw, 0.0f);
        float ssq = h0 * h0 + h1 * h1 + h2 * h2 + h3 * h3;
#pragma unroll
        for (int o = 16; o; o >>= 1) ssq += __shfl_xor_sync(0xffffffffu, ssq, o);
        const float r = rsqrtf(fmaxf(ssq, 1e-12f));
        float4 o4 = {h0 * r, h1 * r, h2 * r, h3 * r};
        *(float4*)(zout + ((size_t)(c * Bn + b0 + w * 4 + i)) * N + lane * 4) = o4;
    }
}

// ---------------------------------------------------------------------------
// 4) Per-(c,b) contrastive term. grid (C, 16) = 128 blocks; 8 warps,
//    2 rows per warp. Parallel label reduction.
// ---------------------------------------------------------------------------
#define ZPAD 132
__global__ __launch_bounds__(256) void loss_kernel(const float* __restrict__ z,
                                                   const int* __restrict__ label) {
    extern __shared__ float zs[];          // [256][ZPAD]
    __shared__ int slab[Bn];
    __shared__ int wsum[8];

    const int c = blockIdx.x;
    const int tid = threadIdx.x;
    const int lane = tid & 31;
    const int warp = tid >> 5;

    const float* zc = z + (size_t)c * Bn * U3;
    for (int idx = tid; idx < Bn * U3 / 4; idx += 256) {
        const int row = idx >> 5;
        const int c4 = idx & 31;
        float4 v = *(const float4*)(zc + (size_t)row * U3 + c4 * 4);
        *(float4*)&zs[row * ZPAD + c4 * 4] = v;
    }
    const int myl = label[tid * Cn + c];
    slab[tid] = myl;
    // parallel reduction of label sum
    int s = myl;
#pragma unroll
    for (int o = 16; o; o >>= 1) s += __shfl_xor_sync(0xffffffffu, s, o);
    if (lane == 0) wsum[warp] = s;
    __syncthreads();
    int nump = 0;
#pragma unroll
    for (int i = 0; i < 8; i++) nump += wsum[i];

    const int bb = blockIdx.y * 16 + warp * 2;   // 2 rows per warp

    int lb[2];
    const float* zb[2];
#pragma unroll
    for (int i = 0; i < 2; i++) {
        lb[i] = slab[bb + i];
        zb[i] = &zs[(bb + i) * ZPAD];
    }

    float es[2] = {0.f, 0.f};
    float ps[2] = {0.f, 0.f};

#pragma unroll
    for (int kk = 0; kk < 8; kk++) {
        const int k = kk * 32 + lane;
        const float* zk = &zs[k * ZPAD];
        float s0 = 0.f, s1 = 0.f;
#pragma unroll
        for (int j = 0; j < U3; j += 4) {
            float4 x  = *(const float4*)(zk + j);
            float4 a0 = *(const float4*)(zb[0] + j);
            float4 a1 = *(const float4*)(zb[1] + j);
            s0 = fmaf(a0.x, x.x, s0); s0 = fmaf(a0.y, x.y, s0);
            s0 = fmaf(a0.z, x.z, s0); s0 = fmaf(a0.w, x.w, s0);
            s1 = fmaf(a1.x, x.x, s1); s1 = fmaf(a1.y, x.y, s1);
            s1 = fmaf(a1.z, x.z, s1); s1 = fmaf(a1.w, x.w, s1);
        }
        const int sk = slab[k];
        float sv[2] = {s0, s1};
#pragma unroll
        for (int i = 0; i < 2; i++) {
            const float ipv = (k == bb + i) ? 0.0f : sv[i] * 2.0f;  // /TEMP
            es[i] += __expf(ipv);
            if (sk == lb[i]) ps[i] += ipv;
        }
    }

#pragma unroll
    for (int i = 0; i < 2; i++) {
#pragma unroll
        for (int o = 16; o; o >>= 1) {
            es[i] += __shfl_xor_sync(0xffffffffu, es[i], o);
            ps[i] += __shfl_xor_sync(0xffffffffu, ps[i], o);
        }
    }
    if (lane == 0) {
#pragma unroll
        for (int i = 0; i < 2; i++) {
            const int numv = lb[i] ? nump : (Bn - nump);
            g_term[c * Bn + bb + i] = ps[i] / (float)numv - logf(es[i]);
        }
    }
}

// ---------------------------------------------------------------------------
// 5) Reduce terms -> losses[c]
// ---------------------------------------------------------------------------
__global__ void final_kernel(float* __restrict__ out) {
    __shared__ float red[Bn];
    const int c = blockIdx.x;
    const int tid = threadIdx.x;
    red[tid] = g_term[c * Bn + tid];
    __syncthreads();
    for (int s = 128; s; s >>= 1) {
        if (tid < s) red[tid] += red[tid + s];
        __syncthreads();
    }
    if (tid == 0) out[(size_t)Cn * Bn * U3 + c] = -red[0];
}

// ---------------------------------------------------------------------------
extern "C" void kernel_launch(void* const* d_in, const int* in_sizes, int n_in,
                              void* d_out, int out_size) {
    const float* ec    = (const float*)d_in[0];
    const float* mask  = (const float*)d_in[1];
    const int*   label = (const int*)d_in[2];
    const float* W1    = (const float*)d_in[3];
    const float* b1    = (const float*)d_in[4];
    const float* W2    = (const float*)d_in[5];
    const float* b2    = (const float*)d_in[6];
    const float* W3    = (const float*)d_in[7];
    const float* b3    = (const float*)d_in[8];
    float* out = (float*)d_out;

    const int loss_smem = Bn * ZPAD * (int)sizeof(float);
    cudaFuncSetAttribute(loss_kernel,
                         cudaFuncAttributeMaxDynamicSharedMemorySize, loss_smem);

    pool_kernel<<<dim3(Bn, 2), 256>>>(ec, mask);
    gemm_relu_kernel<1><<<dim3(U1 / 64, Bn / 64, Cn), 256>>>(W1, b1);
    gemm_relu_kernel<2><<<dim3(U2 / 64, Bn / 64, Cn), 256>>>(W2, b2);
    gemm3_norm_kernel<<<dim3(Bn / 16, Cn), 128>>>(W3, b3, out);
    loss_kernel<<<dim3(Cn, Bn / 16), 256, loss_smem>>>(out, label);
    final_kernel<<<Cn, Bn>>>(out);
}

// round 6
// speedup vs baseline: 1.5020x; 1.0538x over previous
#include <cuda_runtime.h>
#include <math.h>
#include <stdint.h>

#define Bn 256
#define Mn 512
#define Dn 512
#define Cn 8
#define U1 512
#define U2 256
#define U3 128

// Scratch (device-code-only references; never touched from host code)
__device__ float g_pooled[Bn * Dn];          // (B, D)
__device__ float g_h1[Cn * Bn * U1];         // (C, B, 512)
__device__ float g_h2[Cn * Bn * U2];         // (C, B, 256)
__device__ float g_term[Cn * Bn];            // per (c,b) loss term

// ---------------------------------------------------------------------------
// tf32 helpers
// ---------------------------------------------------------------------------
__device__ __forceinline__ uint32_t f2tf(float x) {
    uint32_t r;
    asm("cvt.rna.tf32.f32 %0, %1;" : "=r"(r) : "f"(x));
    return r;
}
// D += A*B  (m16n8k8, A row-major frag, B col-major frag, fp32 accum)
__device__ __forceinline__ void mma8(float* d, const uint32_t* a, const uint32_t* b) {
    asm("mma.sync.aligned.m16n8k8.row.col.f32.tf32.tf32.f32 "
        "{%0,%1,%2,%3}, {%4,%5,%6,%7}, {%8,%9}, {%0,%1,%2,%3};"
        : "+f"(d[0]), "+f"(d[1]), "+f"(d[2]), "+f"(d[3])
        : "r"(a[0]), "r"(a[1]), "r"(a[2]), "r"(a[3]), "r"(b[0]), "r"(b[1]));
}

// ---------------------------------------------------------------------------
// 1) Masked sum pooling: pooled[b,d] = sum_m ec[b,m,d] * (mask[b,m]==0)
// ---------------------------------------------------------------------------
__global__ __launch_bounds__(256) void pool_kernel(const float* __restrict__ ec,
                                                   const float* __restrict__ mask) {
    const int b = blockIdx.x;
    const int dbase = blockIdx.y * 256;
    const int tid = threadIdx.x;

    __shared__ float keep[Mn];
    for (int i = tid; i < Mn; i += 256)
        keep[i] = (mask[b * Mn + i] == 0.0f) ? 1.0f : 0.0f;
    __syncthreads();

    const float* p = ec + ((size_t)b * Mn) * Dn + dbase + tid;
    float a0 = 0.f, a1 = 0.f, a2 = 0.f, a3 = 0.f;
#pragma unroll 4
    for (int m = 0; m < Mn; m += 4) {
        a0 = fmaf(p[(size_t)(m + 0) * Dn], keep[m + 0], a0);
        a1 = fmaf(p[(size_t)(m + 1) * Dn], keep[m + 1], a1);
        a2 = fmaf(p[(size_t)(m + 2) * Dn], keep[m + 2], a2);
        a3 = fmaf(p[(size_t)(m + 3) * Dn], keep[m + 3], a3);
    }
    g_pooled[b * Dn + dbase + tid] = (a0 + a1) + (a2 + a3);
}

// ---------------------------------------------------------------------------
// 2) Layers 1+2 on tensor cores: tf32 mma.m16n8k8 with 2-term split
//    (ah+al), products ah*bh + ah*bl + al*bh (rel err ~2^-22).
//    Block 256 thr = 8 warps (2m x 4n), tile 64x64, warp tile 32x16.
// ---------------------------------------------------------------------------
template <int LAYER>
__global__ __launch_bounds__(256) void gemm_tf32_kernel(
        const float* __restrict__ W, const float* __restrict__ bias) {
    constexpr int K = (LAYER == 1) ? Dn : U1;
    constexpr int N = (LAYER == 1) ? U1 : U2;
    constexpr bool AHASC = (LAYER != 1);
    const float* Aroot = (LAYER == 1) ? g_pooled : g_h1;
    float* Oroot       = (LAYER == 1) ? g_h1     : g_h2;

    const int c  = blockIdx.z;
    const int b0 = blockIdx.y * 64;
    const int n0 = blockIdx.x * 64;
    const int tid = threadIdx.x;
    const int lane = tid & 31;
    const int warp = tid >> 5;
    const int wm = warp >> 2;       // 0..1
    const int wn = warp & 3;        // 0..3
    const int g  = lane >> 2;       // group id 0..7
    const int tg = lane & 3;        // thread in group

    // A tiles m-major (conflict-free A-frag loads), W tiles k-major
    __shared__ uint32_t Ah[64][36], Al[64][36];
    __shared__ uint32_t Wh[32][68], Wl[32][68];

    float acc[2][2][4] = {};

    const float* Ag = Aroot + (AHASC ? (size_t)c * Bn * K : 0) + (size_t)b0 * K;
    const float* Wg = W + (size_t)c * K * N + n0;

    const int arow = tid >> 2;          // 0..63
    const int acol = (tid & 3) * 8;     // 0,8,16,24
    const int wrow = tid >> 3;          // 0..31
    const int wcol = (tid & 7) * 8;     // 0..56

    for (int k0 = 0; k0 < K; k0 += 32) {
        float4 ga0 = *(const float4*)(Ag + (size_t)arow * K + k0 + acol);
        float4 ga1 = *(const float4*)(Ag + (size_t)arow * K + k0 + acol + 4);
        float4 gw0 = *(const float4*)(Wg + (size_t)(k0 + wrow) * N + wcol);
        float4 gw1 = *(const float4*)(Wg + (size_t)(k0 + wrow) * N + wcol + 4);

        __syncthreads();
        {
            float av[8] = {ga0.x, ga0.y, ga0.z, ga0.w, ga1.x, ga1.y, ga1.z, ga1.w};
            uint32_t h[8], l[8];
#pragma unroll
            for (int j = 0; j < 8; j++) {
                h[j] = f2tf(av[j]);
                l[j] = f2tf(av[j] - __uint_as_float(h[j]));
            }
            *(uint4*)&Ah[arow][acol]     = make_uint4(h[0], h[1], h[2], h[3]);
            *(uint4*)&Ah[arow][acol + 4] = make_uint4(h[4], h[5], h[6], h[7]);
            *(uint4*)&Al[arow][acol]     = make_uint4(l[0], l[1], l[2], l[3]);
            *(uint4*)&Al[arow][acol + 4] = make_uint4(l[4], l[5], l[6], l[7]);
        }
        {
            float wv[8] = {gw0.x, gw0.y, gw0.z, gw0.w, gw1.x, gw1.y, gw1.z, gw1.w};
            uint32_t h[8], l[8];
#pragma unroll
            for (int j = 0; j < 8; j++) {
                h[j] = f2tf(wv[j]);
                l[j] = f2tf(wv[j] - __uint_as_float(h[j]));
            }
            *(uint4*)&Wh[wrow][wcol]     = make_uint4(h[0], h[1], h[2], h[3]);
            *(uint4*)&Wh[wrow][wcol + 4] = make_uint4(h[4], h[5], h[6], h[7]);
            *(uint4*)&Wl[wrow][wcol]     = make_uint4(l[0], l[1], l[2], l[3]);
            *(uint4*)&Wl[wrow][wcol + 4] = make_uint4(l[4], l[5], l[6], l[7]);
        }
        __syncthreads();

#pragma unroll
        for (int kk = 0; kk < 4; kk++) {
            const int kb = kk * 8;
            uint32_t ah[2][4], al_[2][4], bh[2][2], bl[2][2];
#pragma unroll
            for (int mi = 0; mi < 2; mi++) {
                const int m = wm * 32 + mi * 16 + g;
                ah[mi][0]  = Ah[m][kb + tg];     ah[mi][1]  = Ah[m + 8][kb + tg];
                ah[mi][2]  = Ah[m][kb + tg + 4]; ah[mi][3]  = Ah[m + 8][kb + tg + 4];
                al_[mi][0] = Al[m][kb + tg];     al_[mi][1] = Al[m + 8][kb + tg];
                al_[mi][2] = Al[m][kb + tg + 4]; al_[mi][3] = Al[m + 8][kb + tg + 4];
            }
#pragma unroll
            for (int ni = 0; ni < 2; ni++) {
                const int n = wn * 16 + ni * 8 + g;
                bh[ni][0] = Wh[kb + tg][n]; bh[ni][1] = Wh[kb + tg + 4][n];
                bl[ni][0] = Wl[kb + tg][n]; bl[ni][1] = Wl[kb + tg + 4][n];
            }
#pragma unroll
            for (int mi = 0; mi < 2; mi++)
#pragma unroll
                for (int ni = 0; ni < 2; ni++) {
                    mma8(acc[mi][ni], ah[mi],  bh[ni]);   // hi*hi
                    mma8(acc[mi][ni], ah[mi],  bl[ni]);   // hi*lo
                    mma8(acc[mi][ni], al_[mi], bh[ni]);   // lo*hi
                }
        }
    }

    // epilogue: bias + relu
#pragma unroll
    for (int mi = 0; mi < 2; mi++) {
#pragma unroll
        for (int ni = 0; ni < 2; ni++) {
            const int ncol = n0 + wn * 16 + ni * 8 + tg * 2;
            const float bx = bias[c * N + ncol];
            const float by = bias[c * N + ncol + 1];
            const int r0 = b0 + wm * 32 + mi * 16 + g;
            float2 o0 = {fmaxf(acc[mi][ni][0] + bx, 0.f),
                         fmaxf(acc[mi][ni][1] + by, 0.f)};
            float2 o1 = {fmaxf(acc[mi][ni][2] + bx, 0.f),
                         fmaxf(acc[mi][ni][3] + by, 0.f)};
            *(float2*)(Oroot + ((size_t)(c * Bn + r0)) * N + ncol)     = o0;
            *(float2*)(Oroot + ((size_t)(c * Bn + r0 + 8)) * N + ncol) = o1;
        }
    }
}

// ---------------------------------------------------------------------------
// 3) Layer 3 fused with L2 normalize (proven, 11.6us).
// ---------------------------------------------------------------------------
__global__ __launch_bounds__(128) void gemm3_norm_kernel(
        const float* __restrict__ W, const float* __restrict__ bias,
        float* __restrict__ zout) {
    constexpr int K = U2;   // 256
    constexpr int N = U3;   // 128
    const int b0 = blockIdx.x * 16;
    const int c  = blockIdx.y;
    const int tid = threadIdx.x;
    const int w = tid >> 5;
    const int lane = tid & 31;

    __shared__ float As[32][20];
    __shared__ float Ws[32][128];

    float acc[4][4] = {};

    const float* Ag = g_h2 + (size_t)c * Bn * K + (size_t)b0 * K;
    const float* Wg = W + (size_t)c * K * N;

    const int arow = tid >> 3;       // 0..15
    const int acol = (tid & 7) * 4;  // 0..28

    float4 areg = *(const float4*)(Ag + (size_t)arow * K + acol);
    float4 wreg[8];
#pragma unroll
    for (int it = 0; it < 8; it++) {
        const int f = it * 128 + tid;
        wreg[it] = *(const float4*)(Wg + (size_t)(f >> 5) * N + (f & 31) * 4);
    }

    for (int k0 = 0; k0 < K; k0 += 32) {
        __syncthreads();
        As[acol + 0][arow] = areg.x; As[acol + 1][arow] = areg.y;
        As[acol + 2][arow] = areg.z; As[acol + 3][arow] = areg.w;
#pragma unroll
        for (int it = 0; it < 8; it++) {
            const int f = it * 128 + tid;
            *(float4*)&Ws[f >> 5][(f & 31) * 4] = wreg[it];
        }
        __syncthreads();

        if (k0 + 32 < K) {
            areg = *(const float4*)(Ag + (size_t)arow * K + k0 + 32 + acol);
#pragma unroll
            for (int it = 0; it < 8; it++) {
                const int f = it * 128 + tid;
                wreg[it] = *(const float4*)(Wg + (size_t)(k0 + 32 + (f >> 5)) * N + (f & 31) * 4);
            }
        }

#pragma unroll
        for (int k = 0; k < 32; k++) {
            float4 av = *(const float4*)&As[k][w * 4];
            float4 wv = *(const float4*)&Ws[k][lane * 4];
            float a[4] = {av.x, av.y, av.z, av.w};
            float ww[4] = {wv.x, wv.y, wv.z, wv.w};
#pragma unroll
            for (int i = 0; i < 4; i++)
#pragma unroll
                for (int j = 0; j < 4; j++)
                    acc[i][j] = fmaf(a[i], ww[j], acc[i][j]);
        }
    }

    const float* bptr = bias + c * N + lane * 4;
    float bx = bptr[0], by = bptr[1], bz = bptr[2], bw = bptr[3];
#pragma unroll
    for (int i = 0; i < 4; i++) {
        float h0 = fmaxf(acc[i][0] + bx, 0.0f);
        float h1 = fmaxf(acc[i][1] + by, 0.0f);
        float h2 = fmaxf(acc[i][2] + bz, 0.0f);
        float h3 = fmaxf(acc[i][3] + bw, 0.0f);
        float ssq = h0 * h0 + h1 * h1 + h2 * h2 + h3 * h3;
#pragma unroll
        for (int o = 16; o; o >>= 1) ssq += __shfl_xor_sync(0xffffffffu, ssq, o);
        const float r = rsqrtf(fmaxf(ssq, 1e-12f));
        float4 o4 = {h0 * r, h1 * r, h2 * r, h3 * r};
        *(float4*)(zout + ((size_t)(c * Bn + b0 + w * 4 + i)) * N + lane * 4) = o4;
    }
}

// ---------------------------------------------------------------------------
// 4) Per-(c,b) contrastive term. grid (C, 16) = 128 blocks; 8 warps,
//    2 rows per warp. Parallel label reduction.
// ---------------------------------------------------------------------------
#define ZPAD 132
__global__ __launch_bounds__(256) void loss_kernel(const float* __restrict__ z,
                                                   const int* __restrict__ label) {
    extern __shared__ float zs[];          // [256][ZPAD]
    __shared__ int slab[Bn];
    __shared__ int wsum[8];

    const int c = blockIdx.x;
    const int tid = threadIdx.x;
    const int lane = tid & 31;
    const int warp = tid >> 5;

    const float* zc = z + (size_t)c * Bn * U3;
    for (int idx = tid; idx < Bn * U3 / 4; idx += 256) {
        const int row = idx >> 5;
        const int c4 = idx & 31;
        float4 v = *(const float4*)(zc + (size_t)row * U3 + c4 * 4);
        *(float4*)&zs[row * ZPAD + c4 * 4] = v;
    }
    const int myl = label[tid * Cn + c];
    slab[tid] = myl;
    int s = myl;
#pragma unroll
    for (int o = 16; o; o >>= 1) s += __shfl_xor_sync(0xffffffffu, s, o);
    if (lane == 0) wsum[warp] = s;
    __syncthreads();
    int nump = 0;
#pragma unroll
    for (int i = 0; i < 8; i++) nump += wsum[i];

    const int bb = blockIdx.y * 16 + warp * 2;   // 2 rows per warp

    int lb[2];
    const float* zb[2];
#pragma unroll
    for (int i = 0; i < 2; i++) {
        lb[i] = slab[bb + i];
        zb[i] = &zs[(bb + i) * ZPAD];
    }

    float es[2] = {0.f, 0.f};
    float ps[2] = {0.f, 0.f};

#pragma unroll
    for (int kk = 0; kk < 8; kk++) {
        const int k = kk * 32 + lane;
        const float* zk = &zs[k * ZPAD];
        float s0 = 0.f, s1 = 0.f;
#pragma unroll
        for (int j = 0; j < U3; j += 4) {
            float4 x  = *(const float4*)(zk + j);
            float4 a0 = *(const float4*)(zb[0] + j);
            float4 a1 = *(const float4*)(zb[1] + j);
            s0 = fmaf(a0.x, x.x, s0); s0 = fmaf(a0.y, x.y, s0);
            s0 = fmaf(a0.z, x.z, s0); s0 = fmaf(a0.w, x.w, s0);
            s1 = fmaf(a1.x, x.x, s1); s1 = fmaf(a1.y, x.y, s1);
            s1 = fmaf(a1.z, x.z, s1); s1 = fmaf(a1.w, x.w, s1);
        }
        const int sk = slab[k];
        float sv[2] = {s0, s1};
#pragma unroll
        for (int i = 0; i < 2; i++) {
            const float ipv = (k == bb + i) ? 0.0f : sv[i] * 2.0f;  // /TEMP
            es[i] += __expf(ipv);
            if (sk == lb[i]) ps[i] += ipv;
        }
    }

#pragma unroll
    for (int i = 0; i < 2; i++) {
#pragma unroll
        for (int o = 16; o; o >>= 1) {
            es[i] += __shfl_xor_sync(0xffffffffu, es[i], o);
            ps[i] += __shfl_xor_sync(0xffffffffu, ps[i], o);
        }
    }
    if (lane == 0) {
#pragma unroll
        for (int i = 0; i < 2; i++) {
            const int numv = lb[i] ? nump : (Bn - nump);
            g_term[c * Bn + bb + i] = ps[i] / (float)numv - logf(es[i]);
        }
    }
}

// ---------------------------------------------------------------------------
// 5) Reduce terms -> losses[c]
// ---------------------------------------------------------------------------
__global__ void final_kernel(float* __restrict__ out) {
    __shared__ float red[Bn];
    const int c = blockIdx.x;
    const int tid = threadIdx.x;
    red[tid] = g_term[c * Bn + tid];
    __syncthreads();
    for (int s = 128; s; s >>= 1) {
        if (tid < s) red[tid] += red[tid + s];
        __syncthreads();
    }
    if (tid == 0) out[(size_t)Cn * Bn * U3 + c] = -red[0];
}

// ---------------------------------------------------------------------------
extern "C" void kernel_launch(void* const* d_in, const int* in_sizes, int n_in,
                              void* d_out, int out_size) {
    const float* ec    = (const float*)d_in[0];
    const float* mask  = (const float*)d_in[1];
    const int*   label = (const int*)d_in[2];
    const float* W1    = (const float*)d_in[3];
    const float* b1    = (const float*)d_in[4];
    const float* W2    = (const float*)d_in[5];
    const float* b2    = (const float*)d_in[6];
    const float* W3    = (const float*)d_in[7];
    const float* b3    = (const float*)d_in[8];
    float* out = (float*)d_out;

    const int loss_smem = Bn * ZPAD * (int)sizeof(float);
    cudaFuncSetAttribute(loss_kernel,
                         cudaFuncAttributeMaxDynamicSharedMemorySize, loss_smem);

    pool_kernel<<<dim3(Bn, 2), 256>>>(ec, mask);
    gemm_tf32_kernel<1><<<dim3(U1 / 64, Bn / 64, Cn), 256>>>(W1, b1);
    gemm_tf32_kernel<2><<<dim3(U2 / 64, Bn / 64, Cn), 256>>>(W2, b2);
    gemm3_norm_kernel<<<dim3(Bn / 16, Cn), 128>>>(W3, b3, out);
    loss_kernel<<<dim3(Cn, Bn / 16), 256, loss_smem>>>(out, label);
    final_kernel<<<Cn, Bn>>>(out);
}